// round 14
// baseline (speedup 1.0000x reference)
#include <cuda_runtime.h>
#include <cuda_bf16.h>
#include <cstdint>
#include <math.h>

#define Bb   8
#define Cc   32
#define Ll   90000
#define DOWNL 22500
#define FLATN 1440000

#define MT    2
#define TOUT  305            // 296 tiles/batch -> 2368 = 148*16 exactly
#define TPBT  296
#define NT    (Bb*TPBT)      // 2368
#define GRIDP 148
#define NTHR  384            // 12 warps x m32 = 384 rows
#define RL_END (64 + TOUT)   // 369: rows [64,369) written

// ---- scratch ----
__device__ float g_skip[Bb*Cc*Ll];
__device__ float g_y[Bb*FLATN];
__device__ float g_o[Bb*64];

__device__ __forceinline__ void mma_bf16(float d[4], const uint32_t a[4], const uint32_t b[2]) {
    asm volatile(
        "mma.sync.aligned.m16n8k16.row.col.f32.bf16.bf16.f32 "
        "{%0,%1,%2,%3}, {%4,%5,%6,%7}, {%8,%9}, {%0,%1,%2,%3};"
        : "+f"(d[0]), "+f"(d[1]), "+f"(d[2]), "+f"(d[3])
        : "r"(a[0]), "r"(a[1]), "r"(a[2]), "r"(a[3]), "r"(b[0]), "r"(b[1]));
}
__device__ __forceinline__ uint32_t pack_hi(float a, float b, uint32_t& lo) {
    __nv_bfloat162 h2 = __floats2bfloat162_rn(a, b);
    float ra = a - __low2float(h2);
    float rb = b - __high2float(h2);
    __nv_bfloat162 l2 = __floats2bfloat162_rn(ra, rb);
    lo = *(uint32_t*)&l2;
    return *(uint32_t*)&h2;
}
__device__ __forceinline__ float2 bf2sum(uint32_t h, uint32_t l) {
    __nv_bfloat162 hh = *(__nv_bfloat162*)&h;
    __nv_bfloat162 ll = *(__nv_bfloat162*)&l;
    return make_float2(__bfloat162float(hh.x) + __bfloat162float(ll.x),
                       __bfloat162float(hh.y) + __bfloat162float(ll.y));
}
// o = tanh(f)*sigmoid(g) = (1-u)/((1+u)(1+v)), u=e^{-2f}, v=e^{-g}
__device__ __forceinline__ float gated(float f, float g) {
    f = fminf(fmaxf(f, -15.f), 15.f);
    g = fminf(fmaxf(g, -30.f), 30.f);
    float u = __expf(-2.f * f);
    float v = __expf(-g);
    return __fdividef(1.f - u, (1.f + u) * (1.f + v));
}
// swizzled sH addressing: conflict-free (rl ≡ r0 mod 4 in every phase)
__device__ __forceinline__ int h_word(int rl, int q) {
    return rl*16 + ((q + ((rl & 3) << 2)) & 15);
}

// ---- SMEM layout (bytes) ----
#define OFF_X     0          // 386 floats
#define OFF_CONV  1568       // 128 floats
#define OFF_BIAS  2080       // 768 floats
#define OFF_W1    5184       // 6 * uint2[64][36] = 110592
#define OFF_W2    115776     // 6 * uint2[64][20] = 61440
#define OFF_H     177216     // uint2[384][16] swizzled = 49152
#define SMEM_TOT  226368

#define W1STR 36
#define W2STR 20

// =========================================================================
// Fused conv0 + 6 blocks; 12 warps x m32, swizzled sH, aD hoisted,
// term-major MMA order; perfect 16-tiles-per-CTA balance
// =========================================================================
__global__ void __launch_bounds__(NTHR)
wn_fused(const float* __restrict__ x,
         const float* __restrict__ w0g, const float* __restrict__ b0g,
         const float* __restrict__ Wf,  const float* __restrict__ bf,
         const float* __restrict__ Wg,  const float* __restrict__ bg,
         const float* __restrict__ Ws,  const float* __restrict__ bs,
         const float* __restrict__ Wr,  const float* __restrict__ br)
{
    extern __shared__ char sm[];
    float* sX    = (float*)(sm + OFF_X);
    float* sConv = (float*)(sm + OFF_CONV);
    float* sBias = (float*)(sm + OFF_BIAS);
    uint2* sW1   = (uint2*)(sm + OFF_W1);
    uint2* sW2   = (uint2*)(sm + OFF_W2);
    uint2* sH    = (uint2*)(sm + OFF_H);

    const int tid = threadIdx.x;

    for (int e = tid; e < 96; e += NTHR) sConv[e] = w0g[e];
    for (int e = tid; e < 32; e += NTHR) sConv[96 + e] = b0g[e];
    for (int e = tid; e < 6*128; e += NTHR) {
        int i = e >> 7, r = e & 127;
        float v = (r < 32)  ? bf[i*32 + r]
                : (r < 64)  ? bg[i*32 + r - 32]
                : (r < 96)  ? bs[i*32 + r - 64]
                :             br[i*32 + r - 96];
        sBias[e] = v;
    }
    for (int e = tid; e < 6*64*32; e += NTHR) {
        int i = e >> 11, rem = e & 2047;
        int n = rem >> 5, kp = rem & 31;
        const float* wfp = Wf + i*2048;
        const float* wgp = Wg + i*2048;
        float v[2];
        #pragma unroll
        for (int q = 0; q < 2; ++q) {
            int k = kp*2 + q;
            v[q] = (n < 32)
                ? ((k < 32) ? wfp[n*64 + k*2] : wfp[n*64 + (k-32)*2 + 1])
                : ((k < 32) ? wgp[(n-32)*64 + k*2] : wgp[(n-32)*64 + (k-32)*2 + 1]);
        }
        uint32_t lo, hi = pack_hi(v[0], v[1], lo);
        sW1[i*64*W1STR + n*W1STR + kp] = make_uint2(hi, lo);
    }
    for (int e = tid; e < 6*64*16; e += NTHR) {
        int i = e >> 10, rem = e & 1023;
        int n = rem >> 4, kp = rem & 15;
        const float* wsp = Ws + i*1024;
        const float* wrp = Wr + i*1024;
        float v0 = (n < 32) ? wsp[n*32 + kp*2]     : wrp[(n-32)*32 + kp*2];
        float v1 = (n < 32) ? wsp[n*32 + kp*2 + 1] : wrp[(n-32)*32 + kp*2 + 1];
        uint32_t lo, hi = pack_hi(v0, v1, lo);
        sW2[i*64*W2STR + n*W2STR + kp] = make_uint2(hi, lo);
    }
    __syncthreads();

    const int w    = tid >> 5;
    const int lane = tid & 31;
    const int r0   = lane >> 2;
    const int tig  = lane & 3;
    const int rb0  = w*32 + r0;     // 12 warps x 32 rows = 384 rows

    for (int tile = blockIdx.x; tile < NT; tile += GRIDP) {
        const int b  = tile / TPBT;
        const int u  = tile - b*TPBT;
        const int g0 = u*TOUT - 64;
        const float* xb = x + (size_t)b * Ll;

        for (int e = tid; e < 386; e += NTHR) {
            int gx = g0 - 2 + e;
            sX[e] = (gx >= 0 && gx < Ll) ? xb[gx] : 0.f;
        }
        __syncthreads();

        // ---- conv0 -> aT regs + sH ----
        uint32_t aTh[MT][2][4], aTl[MT][2][4];
        #pragma unroll
        for (int mt = 0; mt < MT; ++mt) {
            #pragma unroll
            for (int p = 0; p < 4; ++p) {
                #pragma unroll
                for (int half = 0; half < 2; ++half) {
                    const int rl = rb0 + mt*16 + half*8;
                    const int grow = g0 + rl;
                    float x0 = sX[rl+2], xm1 = sX[rl+1], xm2 = sX[rl];
                    const int c0 = p*8 + tig*2;
                    float v0 = sConv[c0*3+2]*x0 + sConv[c0*3+1]*xm1 + sConv[c0*3+0]*xm2 + sConv[96+c0];
                    float v1 = sConv[(c0+1)*3+2]*x0 + sConv[(c0+1)*3+1]*xm1 + sConv[(c0+1)*3+0]*xm2 + sConv[96+c0+1];
                    if (grow < 0 || grow >= Ll) { v0 = 0.f; v1 = 0.f; }
                    uint32_t lo, hi = pack_hi(v0, v1, lo);
                    aTh[mt][p>>1][(p&1)*2+half] = hi;
                    aTl[mt][p>>1][(p&1)*2+half] = lo;
                    sH[h_word(rl, p*4 + tig)] = make_uint2(hi, lo);
                }
            }
        }
        __syncthreads();

        float skipacc[MT][4][4];
        #pragma unroll
        for (int mt = 0; mt < MT; ++mt)
            #pragma unroll
            for (int n = 0; n < 4; ++n)
                #pragma unroll
                for (int j = 0; j < 4; ++j) skipacc[mt][n][j] = 0.f;

        #pragma unroll 1
        for (int i = 0; i < 6; ++i) {
            const int d = 1 << i;
            const uint2* W1b = sW1 + i*(64*W1STR);
            const uint2* W2b = sW2 + i*(64*W2STR);
            const float* bsm = sBias + i*128;

            // ---- dilated fragments: ONE load per block ----
            uint32_t aDh[2][MT][4], aDl[2][MT][4];
            #pragma unroll
            for (int kt = 0; kt < 2; ++kt) {
                #pragma unroll
                for (int mt = 0; mt < MT; ++mt) {
                    int rlA = rb0 + mt*16 - d;     if (rlA < 0) rlA = 0;
                    int rlB = rb0 + mt*16 + 8 - d; if (rlB < 0) rlB = 0;
                    const int q = kt*8 + tig;
                    uint2 v00 = sH[h_word(rlA, q)];
                    uint2 v10 = sH[h_word(rlB, q)];
                    uint2 v01 = sH[h_word(rlA, q + 4)];
                    uint2 v11 = sH[h_word(rlB, q + 4)];
                    aDh[kt][mt][0] = v00.x; aDh[kt][mt][1] = v10.x;
                    aDh[kt][mt][2] = v01.x; aDh[kt][mt][3] = v11.x;
                    aDl[kt][mt][0] = v00.y; aDl[kt][mt][1] = v10.y;
                    aDl[kt][mt][2] = v01.y; aDl[kt][mt][3] = v11.y;
                }
            }

            // ============ GEMM1 (nn-split accs, term-major MMA order) ============
            uint32_t a2h[MT][2][4], a2l[MT][2][4];
            #pragma unroll
            for (int nn = 0; nn < 4; ++nn) {
                float acc[MT][2][4];
                #pragma unroll
                for (int mt = 0; mt < MT; ++mt)
                    #pragma unroll
                    for (int n2 = 0; n2 < 2; ++n2)
                        #pragma unroll
                        for (int j = 0; j < 4; ++j) acc[mt][n2][j] = 0.f;

                // dilated taps: weight cols kt 0..1, A = hoisted aD
                #pragma unroll
                for (int kt = 0; kt < 2; ++kt) {
                    uint2 w0 = W1b[((nn    )*8+r0)*W1STR + kt*8 + tig];
                    uint2 w1 = W1b[((nn    )*8+r0)*W1STR + kt*8 + tig + 4];
                    uint2 w2 = W1b[((nn + 4)*8+r0)*W1STR + kt*8 + tig];
                    uint2 w3 = W1b[((nn + 4)*8+r0)*W1STR + kt*8 + tig + 4];
                    uint32_t bh0[2] = { w0.x, w1.x }, bl0[2] = { w0.y, w1.y };
                    uint32_t bh1[2] = { w2.x, w3.x }, bl1[2] = { w2.y, w3.y };
                    #pragma unroll
                    for (int mt = 0; mt < MT; ++mt) {
                        mma_bf16(acc[mt][0], aDh[kt][mt], bh0);
                        mma_bf16(acc[mt][1], aDh[kt][mt], bh1);
                    }
                    #pragma unroll
                    for (int mt = 0; mt < MT; ++mt) {
                        mma_bf16(acc[mt][0], aDh[kt][mt], bl0);
                        mma_bf16(acc[mt][1], aDh[kt][mt], bl1);
                    }
                    #pragma unroll
                    for (int mt = 0; mt < MT; ++mt) {
                        mma_bf16(acc[mt][0], aDl[kt][mt], bh0);
                        mma_bf16(acc[mt][1], aDl[kt][mt], bh1);
                    }
                }
                // current taps: weight cols kt 2..3, A = held aT
                #pragma unroll
                for (int kt = 0; kt < 2; ++kt) {
                    uint2 w0 = W1b[((nn    )*8+r0)*W1STR + (2+kt)*8 + tig];
                    uint2 w1 = W1b[((nn    )*8+r0)*W1STR + (2+kt)*8 + tig + 4];
                    uint2 w2 = W1b[((nn + 4)*8+r0)*W1STR + (2+kt)*8 + tig];
                    uint2 w3 = W1b[((nn + 4)*8+r0)*W1STR + (2+kt)*8 + tig + 4];
                    uint32_t bh0[2] = { w0.x, w1.x }, bl0[2] = { w0.y, w1.y };
                    uint32_t bh1[2] = { w2.x, w3.x }, bl1[2] = { w2.y, w3.y };
                    #pragma unroll
                    for (int mt = 0; mt < MT; ++mt) {
                        mma_bf16(acc[mt][0], aTh[mt][kt], bh0);
                        mma_bf16(acc[mt][1], aTh[mt][kt], bh1);
                    }
                    #pragma unroll
                    for (int mt = 0; mt < MT; ++mt) {
                        mma_bf16(acc[mt][0], aTh[mt][kt], bl0);
                        mma_bf16(acc[mt][1], aTh[mt][kt], bl1);
                    }
                    #pragma unroll
                    for (int mt = 0; mt < MT; ++mt) {
                        mma_bf16(acc[mt][0], aTl[mt][kt], bh0);
                        mma_bf16(acc[mt][1], aTl[mt][kt], bh1);
                    }
                }
                // gated activation for this nn
                const int c = nn*8 + tig*2;
                const float b0f = bsm[c],    b1f = bsm[c+1];
                const float b0g = bsm[32+c], b1g = bsm[32+c+1];
                const int kt2 = nn >> 1;
                const int ri  = (nn & 1)*2;
                #pragma unroll
                for (int mt = 0; mt < MT; ++mt) {
                    float o0 = gated(acc[mt][0][0] + b0f, acc[mt][1][0] + b0g);
                    float o1 = gated(acc[mt][0][1] + b1f, acc[mt][1][1] + b1g);
                    float o2 = gated(acc[mt][0][2] + b0f, acc[mt][1][2] + b0g);
                    float o3 = gated(acc[mt][0][3] + b1f, acc[mt][1][3] + b1g);
                    a2h[mt][kt2][ri]     = pack_hi(o0, o1, a2l[mt][kt2][ri]);
                    a2h[mt][kt2][ri + 1] = pack_hi(o2, o3, a2l[mt][kt2][ri + 1]);
                }
            }
            __syncthreads();   // all GEMM1 sH reads done before h writes below

            // ============ GEMM2 (nn-split, term-major) + skip/h update ============
            #pragma unroll
            for (int nn = 0; nn < 4; ++nn) {
                float acc[MT][2][4];
                #pragma unroll
                for (int mt = 0; mt < MT; ++mt)
                    #pragma unroll
                    for (int n2 = 0; n2 < 2; ++n2)
                        #pragma unroll
                        for (int j = 0; j < 4; ++j) acc[mt][n2][j] = 0.f;

                #pragma unroll
                for (int kt = 0; kt < 2; ++kt) {
                    uint2 w0 = W2b[((nn    )*8+r0)*W2STR + kt*8 + tig];
                    uint2 w1 = W2b[((nn    )*8+r0)*W2STR + kt*8 + tig + 4];
                    uint2 w2 = W2b[((nn + 4)*8+r0)*W2STR + kt*8 + tig];
                    uint2 w3 = W2b[((nn + 4)*8+r0)*W2STR + kt*8 + tig + 4];
                    uint32_t bh0[2] = { w0.x, w1.x }, bl0[2] = { w0.y, w1.y };
                    uint32_t bh1[2] = { w2.x, w3.x }, bl1[2] = { w2.y, w3.y };
                    #pragma unroll
                    for (int mt = 0; mt < MT; ++mt) {
                        mma_bf16(acc[mt][0], a2h[mt][kt], bh0);
                        mma_bf16(acc[mt][1], a2h[mt][kt], bh1);
                    }
                    #pragma unroll
                    for (int mt = 0; mt < MT; ++mt) {
                        mma_bf16(acc[mt][0], a2h[mt][kt], bl0);
                        mma_bf16(acc[mt][1], a2h[mt][kt], bl1);
                    }
                    #pragma unroll
                    for (int mt = 0; mt < MT; ++mt) {
                        mma_bf16(acc[mt][0], a2l[mt][kt], bh0);
                        mma_bf16(acc[mt][1], a2l[mt][kt], bh1);
                    }
                }
                const int c0 = nn*8 + tig*2;
                const int kt2 = nn >> 1;
                const int ri  = (nn & 1)*2;
                #pragma unroll
                for (int mt = 0; mt < MT; ++mt) {
                    #pragma unroll
                    for (int half = 0; half < 2; ++half) {
                        const int rl = rb0 + mt*16 + half*8;
                        const int grow = g0 + rl;
                        const int j0 = half*2;
                        float2 hp = bf2sum(aTh[mt][kt2][ri+half], aTl[mt][kt2][ri+half]);
                        skipacc[mt][nn][j0]   += acc[mt][0][j0]   + bsm[64+c0];
                        skipacc[mt][nn][j0+1] += acc[mt][0][j0+1] + bsm[64+c0+1];
                        if (i < 5) {
                            float hv0 = hp.x + acc[mt][1][j0]   + bsm[96+c0];
                            float hv1 = hp.y + acc[mt][1][j0+1] + bsm[96+c0+1];
                            if (grow < 0) { hv0 = 0.f; hv1 = 0.f; }
                            uint32_t lo, hi = pack_hi(hv0, hv1, lo);
                            aTh[mt][kt2][ri+half] = hi;
                            aTl[mt][kt2][ri+half] = lo;
                            sH[h_word(rl, nn*4 + tig)] = make_uint2(hi, lo);
                        }
                    }
                }
            }
            if (i < 5) __syncthreads();
        }

        // ---- writeout (rows [64, RL_END) only; tiles overlap by 384-64-TOUT) ----
        #pragma unroll
        for (int mt = 0; mt < MT; ++mt) {
            #pragma unroll
            for (int p = 0; p < 4; ++p) {
                #pragma unroll
                for (int half = 0; half < 2; ++half) {
                    const int rl = rb0 + mt*16 + half*8;
                    if (rl >= 64 && rl < RL_END) {
                        const int grow = g0 + rl;
                        if (grow < Ll) {
                            const int c0 = p*8 + tig*2;
                            const size_t i0 = (size_t)(b*Cc + c0)*Ll + grow;
                            g_skip[i0]      = skipacc[mt][p][half*2];
                            g_skip[i0 + Ll] = skipacc[mt][p][half*2 + 1];
                        }
                    }
                }
            }
        }
    }
}

// ---------------- downsample conv ----------------
__global__ void __launch_bounds__(256)
downsample_kernel(const float* __restrict__ wd, const float* __restrict__ bd)
{
    extern __shared__ float sSk[];     // [32][256] = 32 KB

    int tid = threadIdx.x;
    int b   = blockIdx.y;
    int u0  = blockIdx.x * 64;
    int t0  = u0 * 4;

    const float* skb = g_skip + (size_t)b * Cc * Ll;
    for (int e = tid; e < 32*256; e += 256) {
        int c = e >> 8, j = e & 255;
        int gt = t0 + j;
        sSk[c*256 + j] = (gt < Ll) ? skb[c*Ll + gt] : 0.0f;
    }
    __syncthreads();

    const float4* wd4 = (const float4*)wd;
    int op = tid >> 3;
    int o0 = op, o1 = op + 32;
    int qq = tid & 7;
    float a0[8], a1[8];
    float bd0 = __ldg(bd + o0), bd1 = __ldg(bd + o1);
    #pragma unroll
    for (int i = 0; i < 8; ++i) { a0[i]=bd0; a1[i]=bd1; }

    #pragma unroll 4
    for (int c = 0; c < 32; ++c) {
        float4 w0v = __ldg(wd4 + o0*32 + c);
        float4 w1v = __ldg(wd4 + o1*32 + c);
        const float* sr = sSk + c*256;
        #pragma unroll
        for (int i = 0; i < 8; ++i) {
            float4 sv = *(const float4*)(sr + (i*8 + qq)*4);
            a0[i] += w0v.x*sv.x + w0v.y*sv.y + w0v.z*sv.z + w0v.w*sv.w;
            a1[i] += w1v.x*sv.x + w1v.y*sv.y + w1v.z*sv.z + w1v.w*sv.w;
        }
    }
    float* yb = g_y + (size_t)b * FLATN;
    #pragma unroll
    for (int i = 0; i < 8; ++i) {
        int u = u0 + i*8 + qq;
        if (u < DOWNL) {
            yb[o0*DOWNL + u] = a0[i];
            yb[o1*DOWNL + u] = a1[i];
        }
    }
}

// ---------------- FC ----------------
__global__ void zero_o_kernel() {
    int i = threadIdx.x;
    if (i < Bb*64) g_o[i] = 0.0f;
}

#define FC_CHUNK 1000
__global__ void __launch_bounds__(512)
fc_kernel(const float* __restrict__ fcW)
{
    extern __shared__ float smem[];      // y[8][FC_CHUNK] = 32 KB
    int tid = threadIdx.x;
    int f0  = blockIdx.x * FC_CHUNK;
    int mg  = blockIdx.y;

    for (int e = tid; e < 8*FC_CHUNK/4; e += 512) {
        int b = e / (FC_CHUNK/4), f4 = e - b*(FC_CHUNK/4);
        ((float4*)smem)[b*(FC_CHUNK/4) + f4] =
            *(const float4*)(g_y + (size_t)b*FLATN + f0 + f4*4);
    }
    __syncthreads();

    int w = tid >> 5, lane = tid & 31;
    int m0 = mg*32 + w;
    float acc0[8], acc1[8];
    #pragma unroll
    for (int b = 0; b < 8; ++b) { acc0[b]=0.f; acc1[b]=0.f; }

    const float4* W0 = (const float4*)(fcW + (size_t)m0      * FLATN + f0);
    const float4* W1 = (const float4*)(fcW + (size_t)(m0+16) * FLATN + f0);
    #pragma unroll 2
    for (int i4 = lane; i4 < FC_CHUNK/4; i4 += 32) {
        float4 wv0 = __ldg(W0 + i4);
        float4 wv1 = __ldg(W1 + i4);
        #pragma unroll
        for (int b = 0; b < 8; ++b) {
            float4 yv = ((const float4*)smem)[b*(FC_CHUNK/4) + i4];
            acc0[b] += wv0.x*yv.x + wv0.y*yv.y + wv0.z*yv.z + wv0.w*yv.w;
            acc1[b] += wv1.x*yv.x + wv1.y*yv.y + wv1.z*yv.z + wv1.w*yv.w;
        }
    }
    #pragma unroll
    for (int off = 16; off; off >>= 1) {
        #pragma unroll
        for (int b = 0; b < 8; ++b) {
            acc0[b] += __shfl_xor_sync(0xFFFFFFFFu, acc0[b], off);
            acc1[b] += __shfl_xor_sync(0xFFFFFFFFu, acc1[b], off);
        }
    }
    if (lane == 0) {
        #pragma unroll
        for (int b = 0; b < 8; ++b) {
            atomicAdd(&g_o[b*64 + m0],      acc0[b]);
            atomicAdd(&g_o[b*64 + m0 + 16], acc1[b]);
        }
    }
}

// ---------------- final ----------------
__global__ void final_kernel(const float* __restrict__ eps,
                             const float* __restrict__ fcb,
                             float* __restrict__ out)
{
    int i = threadIdx.x;
    int b = i >> 5, l = i & 31;
    float mu = g_o[b*64 + l]      + fcb[l];
    float lv = g_o[b*64 + 32 + l] + fcb[32 + l];
    float z  = mu + eps[b*32 + l] * expf(0.5f * lv);
    out[i]       = mu;
    out[256 + i] = lv;
    out[512 + i] = z;
}

// ---------------- launch ----------------
extern "C" void kernel_launch(void* const* d_in, const int* in_sizes, int n_in,
                              void* d_out, int out_size)
{
    (void)in_sizes; (void)n_in; (void)out_size;
    const float* x   = (const float*)d_in[0];
    const float* eps = (const float*)d_in[1];
    const float* w0  = (const float*)d_in[2];
    const float* b0  = (const float*)d_in[3];
    const float* Wf  = (const float*)d_in[4];
    const float* bf  = (const float*)d_in[5];
    const float* Wg  = (const float*)d_in[6];
    const float* bg  = (const float*)d_in[7];
    const float* Ws  = (const float*)d_in[8];
    const float* bs  = (const float*)d_in[9];
    const float* Wr  = (const float*)d_in[10];
    const float* br  = (const float*)d_in[11];
    const float* wd  = (const float*)d_in[12];
    const float* bd  = (const float*)d_in[13];
    const float* fcW = (const float*)d_in[14];
    const float* fcb = (const float*)d_in[15];
    float* out = (float*)d_out;

    cudaFuncSetAttribute(wn_fused, cudaFuncAttributeMaxDynamicSharedMemorySize, SMEM_TOT);
    cudaFuncSetAttribute(downsample_kernel, cudaFuncAttributeMaxDynamicSharedMemorySize, 32768);
    cudaFuncSetAttribute(fc_kernel, cudaFuncAttributeMaxDynamicSharedMemorySize, 8*FC_CHUNK*4);

    wn_fused<<<GRIDP, NTHR, SMEM_TOT>>>(x, w0, b0, Wf, bf, Wg, bg, Ws, bs, Wr, br);
    downsample_kernel<<<dim3((DOWNL + 63)/64, Bb), 256, 32768>>>(wd, bd);
    zero_o_kernel<<<1, 512>>>();
    fc_kernel<<<dim3(FLATN/FC_CHUNK, 2), 512, 8*FC_CHUNK*4>>>(fcW);
    final_kernel<<<1, 256>>>(eps, fcb, out);
}

// round 15
// speedup vs baseline: 1.0550x; 1.0550x over previous
#include <cuda_runtime.h>
#include <cuda_bf16.h>
#include <cstdint>
#include <math.h>

#define Bb   8
#define Cc   32
#define Ll   90000
#define DOWNL 22500
#define FLATN 1440000

#define MT    2
#define TOUT  320
#define TPBT  282            // ceil(90000/320)
#define NT    (Bb*TPBT)      // 2256
#define GRIDP 148
#define NTHR  384            // 12 warps x m32 = 384 rows

// ---- scratch ----
__device__ float g_skip[Bb*Cc*Ll];
__device__ float g_y[Bb*FLATN];
__device__ float g_o[Bb*64];

__device__ __forceinline__ void mma_bf16(float d[4], const uint32_t a[4], const uint32_t b[2]) {
    asm volatile(
        "mma.sync.aligned.m16n8k16.row.col.f32.bf16.bf16.f32 "
        "{%0,%1,%2,%3}, {%4,%5,%6,%7}, {%8,%9}, {%0,%1,%2,%3};"
        : "+f"(d[0]), "+f"(d[1]), "+f"(d[2]), "+f"(d[3])
        : "r"(a[0]), "r"(a[1]), "r"(a[2]), "r"(a[3]), "r"(b[0]), "r"(b[1]));
}
__device__ __forceinline__ uint32_t pack_hi(float a, float b, uint32_t& lo) {
    __nv_bfloat162 h2 = __floats2bfloat162_rn(a, b);
    float ra = a - __low2float(h2);
    float rb = b - __high2float(h2);
    __nv_bfloat162 l2 = __floats2bfloat162_rn(ra, rb);
    lo = *(uint32_t*)&l2;
    return *(uint32_t*)&h2;
}
__device__ __forceinline__ float2 bf2sum(uint32_t h, uint32_t l) {
    __nv_bfloat162 hh = *(__nv_bfloat162*)&h;
    __nv_bfloat162 ll = *(__nv_bfloat162*)&l;
    return make_float2(__bfloat162float(hh.x) + __bfloat162float(ll.x),
                       __bfloat162float(hh.y) + __bfloat162float(ll.y));
}
// o = tanh(f)*sigmoid(g) = (1-u)/((1+u)(1+v)), u=e^{-2f}, v=e^{-g}
__device__ __forceinline__ float gated(float f, float g) {
    f = fminf(fmaxf(f, -15.f), 15.f);
    g = fminf(fmaxf(g, -30.f), 30.f);
    float u = __expf(-2.f * f);
    float v = __expf(-g);
    return __fdividef(1.f - u, (1.f + u) * (1.f + v));
}
// swizzled sH addressing: conflict-free (rl ≡ r0 mod 4 in every phase)
__device__ __forceinline__ int h_word(int rl, int q) {
    return rl*16 + ((q + ((rl & 3) << 2)) & 15);
}

// ---- SMEM layout (bytes) ----
#define OFF_X     0          // 386 floats
#define OFF_CONV  1568       // 128 floats
#define OFF_BIAS  2080       // 768 floats
#define OFF_W1    5184       // 6 * uint2[64][36] = 110592
#define OFF_W2    115776     // 6 * uint2[64][20] = 61440
#define OFF_H     177216     // uint2[384][16] swizzled = 49152
#define SMEM_TOT  226368

#define W1STR 36
#define W2STR 20

// =========================================================================
// Fused conv0 + 6 blocks; 12 warps x m32, swizzled sH, aD hoisted,
// term-major MMA order; 3 warps/SMSP for latency hiding
// =========================================================================
__global__ void __launch_bounds__(NTHR)
wn_fused(const float* __restrict__ x,
         const float* __restrict__ w0g, const float* __restrict__ b0g,
         const float* __restrict__ Wf,  const float* __restrict__ bf,
         const float* __restrict__ Wg,  const float* __restrict__ bg,
         const float* __restrict__ Ws,  const float* __restrict__ bs,
         const float* __restrict__ Wr,  const float* __restrict__ br)
{
    extern __shared__ char sm[];
    float* sX    = (float*)(sm + OFF_X);
    float* sConv = (float*)(sm + OFF_CONV);
    float* sBias = (float*)(sm + OFF_BIAS);
    uint2* sW1   = (uint2*)(sm + OFF_W1);
    uint2* sW2   = (uint2*)(sm + OFF_W2);
    uint2* sH    = (uint2*)(sm + OFF_H);

    const int tid = threadIdx.x;

    for (int e = tid; e < 96; e += NTHR) sConv[e] = w0g[e];
    for (int e = tid; e < 32; e += NTHR) sConv[96 + e] = b0g[e];
    for (int e = tid; e < 6*128; e += NTHR) {
        int i = e >> 7, r = e & 127;
        float v = (r < 32)  ? bf[i*32 + r]
                : (r < 64)  ? bg[i*32 + r - 32]
                : (r < 96)  ? bs[i*32 + r - 64]
                :             br[i*32 + r - 96];
        sBias[e] = v;
    }
    for (int e = tid; e < 6*64*32; e += NTHR) {
        int i = e >> 11, rem = e & 2047;
        int n = rem >> 5, kp = rem & 31;
        const float* wfp = Wf + i*2048;
        const float* wgp = Wg + i*2048;
        float v[2];
        #pragma unroll
        for (int q = 0; q < 2; ++q) {
            int k = kp*2 + q;
            v[q] = (n < 32)
                ? ((k < 32) ? wfp[n*64 + k*2] : wfp[n*64 + (k-32)*2 + 1])
                : ((k < 32) ? wgp[(n-32)*64 + k*2] : wgp[(n-32)*64 + (k-32)*2 + 1]);
        }
        uint32_t lo, hi = pack_hi(v[0], v[1], lo);
        sW1[i*64*W1STR + n*W1STR + kp] = make_uint2(hi, lo);
    }
    for (int e = tid; e < 6*64*16; e += NTHR) {
        int i = e >> 10, rem = e & 1023;
        int n = rem >> 4, kp = rem & 15;
        const float* wsp = Ws + i*1024;
        const float* wrp = Wr + i*1024;
        float v0 = (n < 32) ? wsp[n*32 + kp*2]     : wrp[(n-32)*32 + kp*2];
        float v1 = (n < 32) ? wsp[n*32 + kp*2 + 1] : wrp[(n-32)*32 + kp*2 + 1];
        uint32_t lo, hi = pack_hi(v0, v1, lo);
        sW2[i*64*W2STR + n*W2STR + kp] = make_uint2(hi, lo);
    }
    __syncthreads();

    const int w    = tid >> 5;
    const int lane = tid & 31;
    const int r0   = lane >> 2;
    const int tig  = lane & 3;
    const int rb0  = w*32 + r0;     // 12 warps x 32 rows = 384 rows

    for (int tile = blockIdx.x; tile < NT; tile += GRIDP) {
        const int b  = tile / TPBT;
        const int u  = tile - b*TPBT;
        const int g0 = u*TOUT - 64;
        const float* xb = x + (size_t)b * Ll;

        for (int e = tid; e < 386; e += NTHR) {
            int gx = g0 - 2 + e;
            sX[e] = (gx >= 0 && gx < Ll) ? xb[gx] : 0.f;
        }
        __syncthreads();

        // ---- conv0 -> aT regs + sH ----
        uint32_t aTh[MT][2][4], aTl[MT][2][4];
        #pragma unroll
        for (int mt = 0; mt < MT; ++mt) {
            #pragma unroll
            for (int p = 0; p < 4; ++p) {
                #pragma unroll
                for (int half = 0; half < 2; ++half) {
                    const int rl = rb0 + mt*16 + half*8;
                    const int grow = g0 + rl;
                    float x0 = sX[rl+2], xm1 = sX[rl+1], xm2 = sX[rl];
                    const int c0 = p*8 + tig*2;
                    float v0 = sConv[c0*3+2]*x0 + sConv[c0*3+1]*xm1 + sConv[c0*3+0]*xm2 + sConv[96+c0];
                    float v1 = sConv[(c0+1)*3+2]*x0 + sConv[(c0+1)*3+1]*xm1 + sConv[(c0+1)*3+0]*xm2 + sConv[96+c0+1];
                    if (grow < 0 || grow >= Ll) { v0 = 0.f; v1 = 0.f; }
                    uint32_t lo, hi = pack_hi(v0, v1, lo);
                    aTh[mt][p>>1][(p&1)*2+half] = hi;
                    aTl[mt][p>>1][(p&1)*2+half] = lo;
                    sH[h_word(rl, p*4 + tig)] = make_uint2(hi, lo);
                }
            }
        }
        __syncthreads();

        float skipacc[MT][4][4];
        #pragma unroll
        for (int mt = 0; mt < MT; ++mt)
            #pragma unroll
            for (int n = 0; n < 4; ++n)
                #pragma unroll
                for (int j = 0; j < 4; ++j) skipacc[mt][n][j] = 0.f;

        #pragma unroll 1
        for (int i = 0; i < 6; ++i) {
            const int d = 1 << i;
            const uint2* W1b = sW1 + i*(64*W1STR);
            const uint2* W2b = sW2 + i*(64*W2STR);
            const float* bsm = sBias + i*128;

            // ---- dilated fragments: ONE load per block ----
            uint32_t aDh[2][MT][4], aDl[2][MT][4];
            #pragma unroll
            for (int kt = 0; kt < 2; ++kt) {
                #pragma unroll
                for (int mt = 0; mt < MT; ++mt) {
                    int rlA = rb0 + mt*16 - d;     if (rlA < 0) rlA = 0;
                    int rlB = rb0 + mt*16 + 8 - d; if (rlB < 0) rlB = 0;
                    const int q = kt*8 + tig;
                    uint2 v00 = sH[h_word(rlA, q)];
                    uint2 v10 = sH[h_word(rlB, q)];
                    uint2 v01 = sH[h_word(rlA, q + 4)];
                    uint2 v11 = sH[h_word(rlB, q + 4)];
                    aDh[kt][mt][0] = v00.x; aDh[kt][mt][1] = v10.x;
                    aDh[kt][mt][2] = v01.x; aDh[kt][mt][3] = v11.x;
                    aDl[kt][mt][0] = v00.y; aDl[kt][mt][1] = v10.y;
                    aDl[kt][mt][2] = v01.y; aDl[kt][mt][3] = v11.y;
                }
            }

            // ============ GEMM1 (nn-split accs, term-major MMA order) ============
            uint32_t a2h[MT][2][4], a2l[MT][2][4];
            #pragma unroll
            for (int nn = 0; nn < 4; ++nn) {
                float acc[MT][2][4];
                #pragma unroll
                for (int mt = 0; mt < MT; ++mt)
                    #pragma unroll
                    for (int n2 = 0; n2 < 2; ++n2)
                        #pragma unroll
                        for (int j = 0; j < 4; ++j) acc[mt][n2][j] = 0.f;

                // dilated taps: weight cols kt 0..1, A = hoisted aD
                #pragma unroll
                for (int kt = 0; kt < 2; ++kt) {
                    uint2 w0 = W1b[((nn    )*8+r0)*W1STR + kt*8 + tig];
                    uint2 w1 = W1b[((nn    )*8+r0)*W1STR + kt*8 + tig + 4];
                    uint2 w2 = W1b[((nn + 4)*8+r0)*W1STR + kt*8 + tig];
                    uint2 w3 = W1b[((nn + 4)*8+r0)*W1STR + kt*8 + tig + 4];
                    uint32_t bh0[2] = { w0.x, w1.x }, bl0[2] = { w0.y, w1.y };
                    uint32_t bh1[2] = { w2.x, w3.x }, bl1[2] = { w2.y, w3.y };
                    #pragma unroll
                    for (int mt = 0; mt < MT; ++mt) {
                        mma_bf16(acc[mt][0], aDh[kt][mt], bh0);
                        mma_bf16(acc[mt][1], aDh[kt][mt], bh1);
                    }
                    #pragma unroll
                    for (int mt = 0; mt < MT; ++mt) {
                        mma_bf16(acc[mt][0], aDh[kt][mt], bl0);
                        mma_bf16(acc[mt][1], aDh[kt][mt], bl1);
                    }
                    #pragma unroll
                    for (int mt = 0; mt < MT; ++mt) {
                        mma_bf16(acc[mt][0], aDl[kt][mt], bh0);
                        mma_bf16(acc[mt][1], aDl[kt][mt], bh1);
                    }
                }
                // current taps: weight cols kt 2..3, A = held aT
                #pragma unroll
                for (int kt = 0; kt < 2; ++kt) {
                    uint2 w0 = W1b[((nn    )*8+r0)*W1STR + (2+kt)*8 + tig];
                    uint2 w1 = W1b[((nn    )*8+r0)*W1STR + (2+kt)*8 + tig + 4];
                    uint2 w2 = W1b[((nn + 4)*8+r0)*W1STR + (2+kt)*8 + tig];
                    uint2 w3 = W1b[((nn + 4)*8+r0)*W1STR + (2+kt)*8 + tig + 4];
                    uint32_t bh0[2] = { w0.x, w1.x }, bl0[2] = { w0.y, w1.y };
                    uint32_t bh1[2] = { w2.x, w3.x }, bl1[2] = { w2.y, w3.y };
                    #pragma unroll
                    for (int mt = 0; mt < MT; ++mt) {
                        mma_bf16(acc[mt][0], aTh[mt][kt], bh0);
                        mma_bf16(acc[mt][1], aTh[mt][kt], bh1);
                    }
                    #pragma unroll
                    for (int mt = 0; mt < MT; ++mt) {
                        mma_bf16(acc[mt][0], aTh[mt][kt], bl0);
                        mma_bf16(acc[mt][1], aTh[mt][kt], bl1);
                    }
                    #pragma unroll
                    for (int mt = 0; mt < MT; ++mt) {
                        mma_bf16(acc[mt][0], aTl[mt][kt], bh0);
                        mma_bf16(acc[mt][1], aTl[mt][kt], bh1);
                    }
                }
                // gated activation for this nn
                const int c = nn*8 + tig*2;
                const float b0f = bsm[c],    b1f = bsm[c+1];
                const float b0g = bsm[32+c], b1g = bsm[32+c+1];
                const int kt2 = nn >> 1;
                const int ri  = (nn & 1)*2;
                #pragma unroll
                for (int mt = 0; mt < MT; ++mt) {
                    float o0 = gated(acc[mt][0][0] + b0f, acc[mt][1][0] + b0g);
                    float o1 = gated(acc[mt][0][1] + b1f, acc[mt][1][1] + b1g);
                    float o2 = gated(acc[mt][0][2] + b0f, acc[mt][1][2] + b0g);
                    float o3 = gated(acc[mt][0][3] + b1f, acc[mt][1][3] + b1g);
                    a2h[mt][kt2][ri]     = pack_hi(o0, o1, a2l[mt][kt2][ri]);
                    a2h[mt][kt2][ri + 1] = pack_hi(o2, o3, a2l[mt][kt2][ri + 1]);
                }
            }
            __syncthreads();   // all GEMM1 sH reads done before h writes below

            // ============ GEMM2 (nn-split, term-major) + skip/h update ============
            #pragma unroll
            for (int nn = 0; nn < 4; ++nn) {
                float acc[MT][2][4];
                #pragma unroll
                for (int mt = 0; mt < MT; ++mt)
                    #pragma unroll
                    for (int n2 = 0; n2 < 2; ++n2)
                        #pragma unroll
                        for (int j = 0; j < 4; ++j) acc[mt][n2][j] = 0.f;

                #pragma unroll
                for (int kt = 0; kt < 2; ++kt) {
                    uint2 w0 = W2b[((nn    )*8+r0)*W2STR + kt*8 + tig];
                    uint2 w1 = W2b[((nn    )*8+r0)*W2STR + kt*8 + tig + 4];
                    uint2 w2 = W2b[((nn + 4)*8+r0)*W2STR + kt*8 + tig];
                    uint2 w3 = W2b[((nn + 4)*8+r0)*W2STR + kt*8 + tig + 4];
                    uint32_t bh0[2] = { w0.x, w1.x }, bl0[2] = { w0.y, w1.y };
                    uint32_t bh1[2] = { w2.x, w3.x }, bl1[2] = { w2.y, w3.y };
                    #pragma unroll
                    for (int mt = 0; mt < MT; ++mt) {
                        mma_bf16(acc[mt][0], a2h[mt][kt], bh0);
                        mma_bf16(acc[mt][1], a2h[mt][kt], bh1);
                    }
                    #pragma unroll
                    for (int mt = 0; mt < MT; ++mt) {
                        mma_bf16(acc[mt][0], a2h[mt][kt], bl0);
                        mma_bf16(acc[mt][1], a2h[mt][kt], bl1);
                    }
                    #pragma unroll
                    for (int mt = 0; mt < MT; ++mt) {
                        mma_bf16(acc[mt][0], a2l[mt][kt], bh0);
                        mma_bf16(acc[mt][1], a2l[mt][kt], bh1);
                    }
                }
                const int c0 = nn*8 + tig*2;
                const int kt2 = nn >> 1;
                const int ri  = (nn & 1)*2;
                #pragma unroll
                for (int mt = 0; mt < MT; ++mt) {
                    #pragma unroll
                    for (int half = 0; half < 2; ++half) {
                        const int rl = rb0 + mt*16 + half*8;
                        const int grow = g0 + rl;
                        const int j0 = half*2;
                        float2 hp = bf2sum(aTh[mt][kt2][ri+half], aTl[mt][kt2][ri+half]);
                        skipacc[mt][nn][j0]   += acc[mt][0][j0]   + bsm[64+c0];
                        skipacc[mt][nn][j0+1] += acc[mt][0][j0+1] + bsm[64+c0+1];
                        if (i < 5) {
                            float hv0 = hp.x + acc[mt][1][j0]   + bsm[96+c0];
                            float hv1 = hp.y + acc[mt][1][j0+1] + bsm[96+c0+1];
                            if (grow < 0) { hv0 = 0.f; hv1 = 0.f; }
                            uint32_t lo, hi = pack_hi(hv0, hv1, lo);
                            aTh[mt][kt2][ri+half] = hi;
                            aTl[mt][kt2][ri+half] = lo;
                            sH[h_word(rl, nn*4 + tig)] = make_uint2(hi, lo);
                        }
                    }
                }
            }
            if (i < 5) __syncthreads();
        }

        // ---- writeout ----
        #pragma unroll
        for (int mt = 0; mt < MT; ++mt) {
            #pragma unroll
            for (int p = 0; p < 4; ++p) {
                #pragma unroll
                for (int half = 0; half < 2; ++half) {
                    const int rl = rb0 + mt*16 + half*8;
                    if (rl >= 64) {
                        const int grow = g0 + rl;
                        if (grow < Ll) {
                            const int c0 = p*8 + tig*2;
                            const size_t i0 = (size_t)(b*Cc + c0)*Ll + grow;
                            g_skip[i0]      = skipacc[mt][p][half*2];
                            g_skip[i0 + Ll] = skipacc[mt][p][half*2 + 1];
                        }
                    }
                }
            }
        }
    }
}

// ---------------- downsample conv ----------------
__global__ void __launch_bounds__(256)
downsample_kernel(const float* __restrict__ wd, const float* __restrict__ bd)
{
    extern __shared__ float sSk[];     // [32][256] = 32 KB

    int tid = threadIdx.x;
    int b   = blockIdx.y;
    int u0  = blockIdx.x * 64;
    int t0  = u0 * 4;

    const float* skb = g_skip + (size_t)b * Cc * Ll;
    for (int e = tid; e < 32*256; e += 256) {
        int c = e >> 8, j = e & 255;
        int gt = t0 + j;
        sSk[c*256 + j] = (gt < Ll) ? skb[c*Ll + gt] : 0.0f;
    }
    __syncthreads();

    const float4* wd4 = (const float4*)wd;
    int op = tid >> 3;
    int o0 = op, o1 = op + 32;
    int qq = tid & 7;
    float a0[8], a1[8];
    float bd0 = __ldg(bd + o0), bd1 = __ldg(bd + o1);
    #pragma unroll
    for (int i = 0; i < 8; ++i) { a0[i]=bd0; a1[i]=bd1; }

    #pragma unroll 4
    for (int c = 0; c < 32; ++c) {
        float4 w0v = __ldg(wd4 + o0*32 + c);
        float4 w1v = __ldg(wd4 + o1*32 + c);
        const float* sr = sSk + c*256;
        #pragma unroll
        for (int i = 0; i < 8; ++i) {
            float4 sv = *(const float4*)(sr + (i*8 + qq)*4);
            a0[i] += w0v.x*sv.x + w0v.y*sv.y + w0v.z*sv.z + w0v.w*sv.w;
            a1[i] += w1v.x*sv.x + w1v.y*sv.y + w1v.z*sv.z + w1v.w*sv.w;
        }
    }
    float* yb = g_y + (size_t)b * FLATN;
    #pragma unroll
    for (int i = 0; i < 8; ++i) {
        int u = u0 + i*8 + qq;
        if (u < DOWNL) {
            yb[o0*DOWNL + u] = a0[i];
            yb[o1*DOWNL + u] = a1[i];
        }
    }
}

// ---------------- FC ----------------
__global__ void zero_o_kernel() {
    int i = threadIdx.x;
    if (i < Bb*64) g_o[i] = 0.0f;
}

#define FC_CHUNK 2000
__global__ void __launch_bounds__(512, 2)
fc_kernel(const float* __restrict__ fcW)
{
    extern __shared__ float smem[];      // y[8][FC_CHUNK] = 64 KB
    int tid = threadIdx.x;
    int f0  = blockIdx.x * FC_CHUNK;
    int mg  = blockIdx.y;

    for (int e = tid; e < 8*FC_CHUNK/4; e += 512) {
        int b = e / (FC_CHUNK/4), f4 = e - b*(FC_CHUNK/4);
        ((float4*)smem)[b*(FC_CHUNK/4) + f4] =
            *(const float4*)(g_y + (size_t)b*FLATN + f0 + f4*4);
    }
    __syncthreads();

    int w = tid >> 5, lane = tid & 31;
    int m0 = mg*32 + w;
    float acc0[8], acc1[8];
    #pragma unroll
    for (int b = 0; b < 8; ++b) { acc0[b]=0.f; acc1[b]=0.f; }

    const float4* W0 = (const float4*)(fcW + (size_t)m0      * FLATN + f0);
    const float4* W1 = (const float4*)(fcW + (size_t)(m0+16) * FLATN + f0);
    #pragma unroll 2
    for (int i4 = lane; i4 < FC_CHUNK/4; i4 += 32) {
        float4 wv0 = __ldg(W0 + i4);
        float4 wv1 = __ldg(W1 + i4);
        #pragma unroll
        for (int b = 0; b < 8; ++b) {
            float4 yv = ((const float4*)smem)[b*(FC_CHUNK/4) + i4];
            acc0[b] += wv0.x*yv.x + wv0.y*yv.y + wv0.z*yv.z + wv0.w*yv.w;
            acc1[b] += wv1.x*yv.x + wv1.y*yv.y + wv1.z*yv.z + wv1.w*yv.w;
        }
    }
    #pragma unroll
    for (int off = 16; off; off >>= 1) {
        #pragma unroll
        for (int b = 0; b < 8; ++b) {
            acc0[b] += __shfl_xor_sync(0xFFFFFFFFu, acc0[b], off);
            acc1[b] += __shfl_xor_sync(0xFFFFFFFFu, acc1[b], off);
        }
    }
    if (lane == 0) {
        #pragma unroll
        for (int b = 0; b < 8; ++b) {
            atomicAdd(&g_o[b*64 + m0],      acc0[b]);
            atomicAdd(&g_o[b*64 + m0 + 16], acc1[b]);
        }
    }
}

// ---------------- final ----------------
__global__ void final_kernel(const float* __restrict__ eps,
                             const float* __restrict__ fcb,
                             float* __restrict__ out)
{
    int i = threadIdx.x;
    int b = i >> 5, l = i & 31;
    float mu = g_o[b*64 + l]      + fcb[l];
    float lv = g_o[b*64 + 32 + l] + fcb[32 + l];
    float z  = mu + eps[b*32 + l] * expf(0.5f * lv);
    out[i]       = mu;
    out[256 + i] = lv;
    out[512 + i] = z;
}

// ---------------- launch ----------------
extern "C" void kernel_launch(void* const* d_in, const int* in_sizes, int n_in,
                              void* d_out, int out_size)
{
    (void)in_sizes; (void)n_in; (void)out_size;
    const float* x   = (const float*)d_in[0];
    const float* eps = (const float*)d_in[1];
    const float* w0  = (const float*)d_in[2];
    const float* b0  = (const float*)d_in[3];
    const float* Wf  = (const float*)d_in[4];
    const float* bf  = (const float*)d_in[5];
    const float* Wg  = (const float*)d_in[6];
    const float* bg  = (const float*)d_in[7];
    const float* Ws  = (const float*)d_in[8];
    const float* bs  = (const float*)d_in[9];
    const float* Wr  = (const float*)d_in[10];
    const float* br  = (const float*)d_in[11];
    const float* wd  = (const float*)d_in[12];
    const float* bd  = (const float*)d_in[13];
    const float* fcW = (const float*)d_in[14];
    const float* fcb = (const float*)d_in[15];
    float* out = (float*)d_out;

    cudaFuncSetAttribute(wn_fused, cudaFuncAttributeMaxDynamicSharedMemorySize, SMEM_TOT);
    cudaFuncSetAttribute(downsample_kernel, cudaFuncAttributeMaxDynamicSharedMemorySize, 32768);
    cudaFuncSetAttribute(fc_kernel, cudaFuncAttributeMaxDynamicSharedMemorySize, 8*FC_CHUNK*4);

    wn_fused<<<GRIDP, NTHR, SMEM_TOT>>>(x, w0, b0, Wf, bf, Wg, bg, Ws, bs, Wr, br);
    downsample_kernel<<<dim3((DOWNL + 63)/64, Bb), 256, 32768>>>(wd, bd);
    zero_o_kernel<<<1, 512>>>();
    fc_kernel<<<dim3(FLATN/FC_CHUNK, 2), 512, 8*FC_CHUNK*4>>>(fcW);
    final_kernel<<<1, 256>>>(eps, fcb, out);
}